// round 17
// baseline (speedup 1.0000x reference)
#include <cuda_runtime.h>
#include <cuda_bf16.h>
#include <cuda_fp16.h>
#include <math.h>
#include <stdint.h>

#define NN 4096
#define NW 128
#define H 4
#define F1 128
#define F2 32
#define HN (H * NN)
#define IN_F 512
#define HID1 64
#define OUT_F 16
#define LRELU 0.2f
#define BN_EPS 1e-5f

// ---------------- scratch ----------------
__device__ float         g_h1[NN * 512];
__device__ float         g_x2[NN * HID1];
__device__ float         g_h2[NN * 128];
__device__ float         g_x3[NN * 128];
__device__ float         g_z4[NN * OUT_F];
__device__ float         g_sc1[6 * HN];
__device__ float         g_sc2[6 * HN];
__device__ __half        g_sch1[2 * HN];
__device__ __half        g_sch2[2 * HN];
__device__ unsigned      g_mask[NN * NW];
__device__ float         g_bnpart[32 * 2 * 64];
__device__ __half        g_h1th[512 * NN];
__device__ __half        g_h2th[128 * NN];
__device__ __nv_bfloat16 g_ah[NN * 512];
__device__ __nv_bfloat16 g_al[NN * 512];
__device__ __nv_bfloat16 g_wth[512 * 512];
__device__ __nv_bfloat16 g_wtl[512 * 512];
__device__ __nv_bfloat16 g_lw1th[HID1 * 512];
__device__ __nv_bfloat16 g_lw1tl[HID1 * 512];
__device__ __nv_bfloat16 g_w2th[128 * HID1];
__device__ __nv_bfloat16 g_w2tl[128 * HID1];

// ================= helpers =================
__device__ __forceinline__ uint32_t smem_u32(const void* p) {
    uint32_t a;
    asm("{ .reg .u64 t; cvta.to.shared.u64 t, %1; cvt.u32.u64 %0, t; }" : "=r"(a) : "l"(p));
    return a;
}
__device__ __forceinline__ void cp16(uint32_t dst, const void* src) {
    asm volatile("cp.async.cg.shared.global [%0], [%1], 16;" :: "r"(dst), "l"(src));
}
__device__ __forceinline__ void cp8(uint32_t dst, const void* src) {
    asm volatile("cp.async.ca.shared.global [%0], [%1], 8;" :: "r"(dst), "l"(src));
}
#define CP_COMMIT() asm volatile("cp.async.commit_group;" ::: "memory")
#define CP_WAIT1()  asm volatile("cp.async.wait_group 1;" ::: "memory")

__device__ __forceinline__ void mma16816(float* c,
    uint32_t a0, uint32_t a1, uint32_t a2, uint32_t a3, uint32_t b0, uint32_t b1) {
    asm volatile(
        "mma.sync.aligned.m16n8k16.row.col.f32.bf16.bf16.f32 "
        "{%0,%1,%2,%3}, {%4,%5,%6,%7}, {%8,%9}, {%0,%1,%2,%3};"
        : "+f"(c[0]), "+f"(c[1]), "+f"(c[2]), "+f"(c[3])
        : "r"(a0), "r"(a1), "r"(a2), "r"(a3), "r"(b0), "r"(b1));
}
__device__ __forceinline__ void mma16816h(float* c,
    uint32_t a0, uint32_t a1, uint32_t a2, uint32_t a3, uint32_t b0, uint32_t b1) {
    asm volatile(
        "mma.sync.aligned.m16n8k16.row.col.f32.f16.f16.f32 "
        "{%0,%1,%2,%3}, {%4,%5,%6,%7}, {%8,%9}, {%0,%1,%2,%3};"
        : "+f"(c[0]), "+f"(c[1]), "+f"(c[2]), "+f"(c[3])
        : "r"(a0), "r"(a1), "r"(a2), "r"(a3), "r"(b0), "r"(b1));
}
__device__ __forceinline__ void ldsm4(uint32_t& r0, uint32_t& r1, uint32_t& r2, uint32_t& r3,
                                      uint32_t addr) {
    asm volatile("ldmatrix.sync.aligned.m8n8.x4.shared.b16 {%0,%1,%2,%3}, [%4];"
                 : "=r"(r0), "=r"(r1), "=r"(r2), "=r"(r3) : "r"(addr));
}
__device__ __forceinline__ uint32_t wgen2(__half2 Eh, __half2 eh, __half2 Ev, __half2 e2,
                                          unsigned w, int bit) {
    __half2 v = __hmax2(__hmul2(Eh, Ev), __hmul2(eh, e2));
    uint32_t u = *(uint32_t*)&v;
    uint32_t lo = ((w >> bit) & 1u) ? 0x0000FFFFu : 0u;
    uint32_t hi = ((w >> (bit + 1)) & 1u) ? 0xFFFF0000u : 0u;
    return u & (lo | hi);
}

// ---------------- adjacency -> bitmask ----------------
__global__ void k_pack_mask(const int* __restrict__ adj) {
    int gw   = (blockIdx.x * blockDim.x + threadIdx.x) >> 5;
    int lane = threadIdx.x & 31;
    int v = adj[(size_t)gw * 32 + lane];
    unsigned m = __ballot_sync(0xffffffffu, v > 0);
    if (lane == 0) g_mask[gw] = m;
}

// ---------------- elementwise fp32 -> bf16 hi/lo split ----------------
__global__ void k_split_bf16(const float* __restrict__ in,
                             __nv_bfloat16* __restrict__ oh,
                             __nv_bfloat16* __restrict__ ol) {
    int idx = blockIdx.x * blockDim.x + threadIdx.x;
    float4 v = ((const float4*)in)[idx];
    __nv_bfloat162 h0 = __floats2bfloat162_rn(v.x, v.y);
    __nv_bfloat162 h1 = __floats2bfloat162_rn(v.z, v.w);
    __nv_bfloat162 l0 = __floats2bfloat162_rn(v.x - __bfloat162float(h0.x),
                                              v.y - __bfloat162float(h0.y));
    __nv_bfloat162 l1 = __floats2bfloat162_rn(v.z - __bfloat162float(h1.x),
                                              v.w - __bfloat162float(h1.y));
    ((__nv_bfloat162*)oh)[idx * 2] = h0;
    ((__nv_bfloat162*)oh)[idx * 2 + 1] = h1;
    ((__nv_bfloat162*)ol)[idx * 2] = l0;
    ((__nv_bfloat162*)ol)[idx * 2 + 1] = l1;
}

// ---------------- transpose fp32 [R,C] -> bf16 hi/lo [C,R] ----------------
__global__ void k_transpose_split(const float* __restrict__ in,
                                  __nv_bfloat16* __restrict__ oh,
                                  __nv_bfloat16* __restrict__ ol, int R, int C) {
    __shared__ float tile[32][33];
    int r0 = blockIdx.x * 32, c0 = blockIdx.y * 32;
    int tx = threadIdx.x, ty = threadIdx.y;
#pragma unroll
    for (int q = 0; q < 4; q++)
        tile[ty * 4 + q][tx] = in[(size_t)(r0 + ty * 4 + q) * C + c0 + tx];
    __syncthreads();
#pragma unroll
    for (int q = 0; q < 4; q++) {
        float v = tile[tx][ty * 4 + q];
        __nv_bfloat16 hi = __float2bfloat16(v);
        float lo = v - __bfloat162float(hi);
        size_t o = (size_t)(c0 + ty * 4 + q) * R + r0 + tx;
        oh[o] = hi;
        ol[o] = __float2bfloat16(lo);
    }
}

// ---------------- transpose fp32 [R,C] -> fp16 [C,R] ----------------
__global__ void k_transpose_f16(const float* __restrict__ in,
                                __half* __restrict__ oh, int R, int C) {
    __shared__ float tile[32][33];
    int r0 = blockIdx.x * 32, c0 = blockIdx.y * 32;
    int tx = threadIdx.x, ty = threadIdx.y;
#pragma unroll
    for (int q = 0; q < 4; q++)
        tile[ty * 4 + q][tx] = in[(size_t)(r0 + ty * 4 + q) * C + c0 + tx];
    __syncthreads();
#pragma unroll
    for (int q = 0; q < 4; q++) {
        size_t o = (size_t)(c0 + ty * 4 + q) * R + r0 + tx;
        oh[o] = __float2half_rn(tile[tx][ty * 4 + q]);
    }
}

// ================ split-bf16 HMMA GEMM, 3-stage pipeline ================
template <int BN, int NWARP>
__device__ __forceinline__ void gemm_load(int t, int m0, int n0, int c, int buf,
                                          uint32_t sb, int K,
                                          const __nv_bfloat16* Ah, const __nv_bfloat16* Al,
                                          const __nv_bfloat16* Bh, const __nv_bfloat16* Bl) {
    constexpr int AB = 16384;
    constexpr int BB = BN * 128;
    constexpr int STAGE = 2 * AB + 2 * BB;
    uint32_t base = sb + buf * STAGE;
#pragma unroll
    for (int idx = t; idx < 1024; idx += NWARP * 32) {
        int m = idx >> 3, q = idx & 7;
        uint32_t off = base + (uint32_t)(m * 128 + ((q ^ (m & 7)) << 4));
        size_t src = (size_t)(m0 + m) * K + c * 64 + q * 8;
        cp16(off, Ah + src);
        cp16(off + AB, Al + src);
    }
#pragma unroll
    for (int idx = t; idx < BN * 8; idx += NWARP * 32) {
        int n = idx >> 3, q = idx & 7;
        uint32_t off = base + 2 * AB + (uint32_t)(n * 128 + ((q ^ (n & 7)) << 4));
        size_t src = (size_t)(n0 + n) * K + c * 64 + q * 8;
        cp16(off, Bh + src);
        cp16(off + BB, Bl + src);
    }
}

template <int BN, int NWARP>
__global__ __launch_bounds__(NWARP * 32) void k_gemm_hmma(
    const __nv_bfloat16* __restrict__ Ah, const __nv_bfloat16* __restrict__ Al,
    const __nv_bfloat16* __restrict__ Bh, const __nv_bfloat16* __restrict__ Bl,
    const float* __restrict__ bias, float* __restrict__ C, int K, int Ntot) {
    constexpr int AB = 16384;
    constexpr int BB = BN * 128;
    constexpr int STAGE = 2 * AB + 2 * BB;
    extern __shared__ char sm[];
    uint32_t sb = smem_u32(sm);
    int t = threadIdx.x, wid = t >> 5, lane = t & 31;
    int m0 = blockIdx.x * 128, n0 = blockIdx.y * BN;
    int wm = (wid & 3) * 32, wn = (wid >> 2) * 32;
    int g = lane >> 2, tig = lane & 3;
    int nc = K >> 6;

    int arow = (lane & 7) + ((lane >> 3) & 1) * 8;
    int ahalf = lane >> 4;
    int brow = ((lane >> 4) << 3) + (lane & 7);
    int bhalf = (lane >> 3) & 1;

    float acc[2][4][4];
#pragma unroll
    for (int mt = 0; mt < 2; mt++)
#pragma unroll
        for (int nt = 0; nt < 4; nt++)
#pragma unroll
            for (int q = 0; q < 4; q++) acc[mt][nt][q] = 0.f;

    gemm_load<BN, NWARP>(t, m0, n0, 0, 0, sb, K, Ah, Al, Bh, Bl);
    CP_COMMIT();
    if (nc > 1) gemm_load<BN, NWARP>(t, m0, n0, 1, 1, sb, K, Ah, Al, Bh, Bl);
    CP_COMMIT();

    for (int c = 0; c < nc; c++) {
        int buf = c % 3;
        CP_WAIT1();
        __syncthreads();
        if (c + 2 < nc)
            gemm_load<BN, NWARP>(t, m0, n0, c + 2, (c + 2) % 3, sb, K, Ah, Al, Bh, Bl);
        CP_COMMIT();
        uint32_t base = sb + buf * STAGE;
#pragma unroll
        for (int ks = 0; ks < 4; ks++) {
            uint32_t ahf[2][4], alf[2][4], bhf[2][4], blf[2][4];
#pragma unroll
            for (int mt = 0; mt < 2; mt++) {
                int r = wm + mt * 16 + arow;
                int slot = 2 * ks + ahalf;
                uint32_t ad = base + (uint32_t)(r * 128 + ((slot ^ (r & 7)) << 4));
                ldsm4(ahf[mt][0], ahf[mt][1], ahf[mt][2], ahf[mt][3], ad);
                ldsm4(alf[mt][0], alf[mt][1], alf[mt][2], alf[mt][3], ad + AB);
            }
#pragma unroll
            for (int np = 0; np < 2; np++) {
                int r = wn + np * 16 + brow;
                int slot = 2 * ks + bhalf;
                uint32_t bd = base + 2 * AB + (uint32_t)(r * 128 + ((slot ^ (r & 7)) << 4));
                ldsm4(bhf[np][0], bhf[np][1], bhf[np][2], bhf[np][3], bd);
                ldsm4(blf[np][0], blf[np][1], blf[np][2], blf[np][3], bd + BB);
            }
#pragma unroll
            for (int mt = 0; mt < 2; mt++)
#pragma unroll
                for (int nt = 0; nt < 4; nt++) {
                    int np = nt >> 1, sel = (nt & 1) * 2;
                    mma16816(acc[mt][nt], ahf[mt][0], ahf[mt][1], ahf[mt][2], ahf[mt][3],
                             bhf[np][sel], bhf[np][sel + 1]);
                }
#pragma unroll
            for (int mt = 0; mt < 2; mt++)
#pragma unroll
                for (int nt = 0; nt < 4; nt++) {
                    int np = nt >> 1, sel = (nt & 1) * 2;
                    mma16816(acc[mt][nt], ahf[mt][0], ahf[mt][1], ahf[mt][2], ahf[mt][3],
                             blf[np][sel], blf[np][sel + 1]);
                }
#pragma unroll
            for (int mt = 0; mt < 2; mt++)
#pragma unroll
                for (int nt = 0; nt < 4; nt++) {
                    int np = nt >> 1, sel = (nt & 1) * 2;
                    mma16816(acc[mt][nt], alf[mt][0], alf[mt][1], alf[mt][2], alf[mt][3],
                             bhf[np][sel], bhf[np][sel + 1]);
                }
        }
    }
#pragma unroll
    for (int mt = 0; mt < 2; mt++)
#pragma unroll
        for (int nt = 0; nt < 4; nt++) {
            int row = m0 + wm + mt * 16 + g;
            int col = n0 + wn + nt * 8 + tig * 2;
            float bv0 = bias ? bias[col] : 0.f;
            float bv1 = bias ? bias[col + 1] : 0.f;
            float2 v0 = make_float2(acc[mt][nt][0] + bv0, acc[mt][nt][1] + bv1);
            float2 v1 = make_float2(acc[mt][nt][2] + bv0, acc[mt][nt][3] + bv1);
            *(float2*)&C[(size_t)row * Ntot + col] = v0;
            *(float2*)&C[(size_t)(row + 8) * Ntot + col] = v1;
        }
}

// ---------------- fp32 GEMM for lin2 ----------------
template <int BM, int BN, int BK, int TM, int TN>
__global__ void k_gemm_bias(const float* __restrict__ A, const float* __restrict__ B,
                            const float* __restrict__ bias, float* __restrict__ C,
                            int M, int Nn, int K) {
    constexpr int THREADS = (BM / TM) * (BN / TN);
    __shared__ float As[BM][BK + 1];
    __shared__ float Bs[BK][BN + 1];
    int tid = threadIdx.x;
    int rm = tid / (BN / TN);
    int rn = tid % (BN / TN);
    int m0 = blockIdx.y * BM, n0 = blockIdx.x * BN;
    float acc[TM][TN];
#pragma unroll
    for (int m = 0; m < TM; m++)
#pragma unroll
        for (int n = 0; n < TN; n++) acc[m][n] = 0.f;

    for (int k0 = 0; k0 < K; k0 += BK) {
        for (int idx = tid; idx < BM * BK; idx += THREADS) {
            int r = idx / BK, c = idx % BK;
            As[r][c] = A[(size_t)(m0 + r) * K + k0 + c];
        }
        for (int idx = tid; idx < BK * BN; idx += THREADS) {
            int r = idx / BN, c = idx % BN;
            Bs[r][c] = B[(size_t)(k0 + r) * Nn + n0 + c];
        }
        __syncthreads();
#pragma unroll
        for (int kk = 0; kk < BK; kk++) {
            float a[TM], b[TN];
#pragma unroll
            for (int m = 0; m < TM; m++) a[m] = As[rm * TM + m][kk];
#pragma unroll
            for (int n = 0; n < TN; n++) b[n] = Bs[kk][rn * TN + n];
#pragma unroll
            for (int m = 0; m < TM; m++)
#pragma unroll
                for (int n = 0; n < TN; n++) acc[m][n] = fmaf(a[m], b[n], acc[m][n]);
        }
        __syncthreads();
    }
#pragma unroll
    for (int m = 0; m < TM; m++) {
        int row = m0 + rm * TM + m;
#pragma unroll
        for (int n = 0; n < TN; n++) {
            int col = n0 + rn * TN + n;
            float v = acc[m][n];
            if (bias) v += bias[col];
            C[(size_t)row * Nn + col] = v;
        }
    }
}

// ---------------- per-node scores ----------------
template <int F>
__global__ void k_attn_scores(const float* __restrict__ hfeat,
                              const float* __restrict__ a_src,
                              const float* __restrict__ a_dst,
                              float* __restrict__ sc,
                              __half* __restrict__ sch) {
    int n = blockIdx.x * (blockDim.x >> 5) + (threadIdx.x >> 5);
    int lane = threadIdx.x & 31;
    if (n >= NN) return;
    const float* row = hfeat + (size_t)n * (H * F);
#pragma unroll
    for (int h = 0; h < H; h++) {
        float ss = 0.f, sd = 0.f;
        for (int k = lane; k < F; k += 32) {
            float v = row[h * F + k];
            ss = fmaf(v, a_src[h * F + k], ss);
            sd = fmaf(v, a_dst[h * F + k], sd);
        }
#pragma unroll
        for (int o = 16; o; o >>= 1) {
            ss += __shfl_xor_sync(0xffffffffu, ss, o);
            sd += __shfl_xor_sync(0xffffffffu, sd, o);
        }
        if (lane == 0) {
            int idx = h * NN + n;
            sc[1 * HN + idx] = expf(ss);
            sc[2 * HN + idx] = expf(LRELU * ss);
            sch[idx]      = __float2half_rn(expf(sd));
            sch[HN + idx] = __float2half_rn(expf(LRELU * sd));
        }
    }
}

// ================ GAT aggregation: full-K, fused normalize epilogue ================
template <int F>
__device__ __forceinline__ void load_chunk(int t, int head, int i0, int c, int buf,
                                           char* BtB, unsigned* mk, __half* edh,
                                           const __half* hTh, const __half* sch) {
    constexpr int BT = F * 128;
    char* dst = BtB + buf * BT;
    for (int idx = t; idx < F * 8; idx += 256) {
        int f = idx >> 3, q = idx & 7;
        uint32_t off = (uint32_t)(f * 128 + (((q ^ (f & 7)) << 4)));
        cp16(smem_u32(dst + off), hTh + (size_t)(head * F + f) * NN + c * 64 + q * 8);
    }
    if (t < 128) cp8(smem_u32(mk + buf * 256 + t * 2), &g_mask[(size_t)(i0 + t) * NW + c * 2]);
    if (t < 16) {
        int a = t >> 3, q = t & 7;
        cp16(smem_u32(edh + buf * 128 + a * 64 + q * 8),
             &sch[(size_t)a * HN + head * NN + c * 64 + q * 8]);
    }
}

template <int F, bool SPLIT>
__global__ __launch_bounds__(256) void k_gat_hmma(const __half* __restrict__ hTh,
                                                  const float* __restrict__ sc,
                                                  const __half* __restrict__ sch,
                                                  float* __restrict__ out,
                                                  __nv_bfloat16* __restrict__ ohi,
                                                  __nv_bfloat16* __restrict__ olo) {
    constexpr int BT = F * 128;
    constexpr int MPF = F / 16;
    constexpr uint32_t ONES = 0x3C003C00u;
    extern __shared__ char smem[];
    char* BtB = smem;                               // [3][BT]
    unsigned* mk = (unsigned*)(smem + 3 * BT);      // [3][256]
    __half* edh = (__half*)(smem + 3 * BT + 3072);  // [3][128]

    int t = threadIdx.x, wid = t >> 5, lane = t & 31;
    int g = lane >> 2, tig = lane & 3;
    int head = blockIdx.y, i0 = blockIdx.x * 128;
    uint32_t sb = smem_u32(smem);

    int r0 = wid * 16 + g, r1 = r0 + 8;
    const float* scb = sc + head * NN + i0;
    __half2 E0h = __float2half2_rn(scb[HN + r0]);
    __half2 e0h = __float2half2_rn(scb[2 * HN + r0]);
    __half2 E1h = __float2half2_rn(scb[HN + r1]);
    __half2 e1h = __float2half2_rn(scb[2 * HN + r1]);

    int flr = ((lane >> 4) & 1) * 8 + (lane & 7);
    int qb = (lane >> 3) & 1;
    int sxw = flr & 7;
    uint32_t fcol = (uint32_t)(flr * 128);

    float acc[2 * MPF][4];
#pragma unroll
    for (int nt = 0; nt < 2 * MPF; nt++)
#pragma unroll
        for (int q = 0; q < 4; q++) acc[nt][q] = 0.f;
    float accd[4] = {0.f, 0.f, 0.f, 0.f};

    load_chunk<F>(t, head, i0, 0, 0, BtB, mk, edh, hTh, sch);
    CP_COMMIT();
    load_chunk<F>(t, head, i0, 1, 1, BtB, mk, edh, hTh, sch);
    CP_COMMIT();

    for (int cc = 0; cc < 64; cc++) {
        int b = cc % 3;
        CP_WAIT1();
        __syncthreads();
        if (cc < 62)
            load_chunk<F>(t, head, i0, cc + 2, (cc + 2) % 3, BtB, mk, edh, hTh, sch);
        CP_COMMIT();
        unsigned* mkb = mk + b * 256;
        unsigned m0a = mkb[r0 * 2], m0b = mkb[r0 * 2 + 1];
        unsigned m1a = mkb[r1 * 2], m1b = mkb[r1 * 2 + 1];
        const __half2* eh = (const __half2*)(edh + b * 128);
        uint32_t bufbase = sb + (uint32_t)(b * BT);
#pragma unroll
        for (int ks = 0; ks < 4; ks++) {
            int jh = (ks * 16 + tig * 2) >> 1;
            __half2 EvL = eh[jh];
            __half2 EvH = eh[jh + 4];
            __half2 e2L = eh[32 + jh];
            __half2 e2H = eh[32 + jh + 4];
            int bit = (ks & 1) * 16 + tig * 2;
            unsigned w0 = (ks < 2) ? m0a : m0b;
            unsigned w1 = (ks < 2) ? m1a : m1b;

            uint32_t A0 = wgen2(E0h, e0h, EvL, e2L, w0, bit);
            uint32_t A1 = wgen2(E1h, e1h, EvL, e2L, w1, bit);
            uint32_t A2 = wgen2(E0h, e0h, EvH, e2H, w0, bit + 8);
            uint32_t A3 = wgen2(E1h, e1h, EvH, e2H, w1, bit + 8);

            mma16816h(accd, A0, A1, A2, A3, ONES, ONES);

            uint32_t swz = (uint32_t)((((2 * ks + qb) ^ sxw) << 4));
#pragma unroll
            for (int mp = 0; mp < MPF; mp++) {
                uint32_t ad = bufbase + fcol + (uint32_t)(mp * 2048) + swz;
                uint32_t bh0, bh1, bh2, bh3;
                ldsm4(bh0, bh1, bh2, bh3, ad);
                mma16816h(acc[2 * mp],     A0, A1, A2, A3, bh0, bh1);
                mma16816h(acc[2 * mp + 1], A0, A1, A2, A3, bh2, bh3);
            }
        }
    }
    // full denominators live in-register (ones-columns are identical across tig)
    float iv0 = 1.f / accd[0];
    float iv1 = 1.f / accd[2];
#pragma unroll
    for (int nt = 0; nt < 2 * MPF; nt++) {
        int col = head * F + nt * 8 + tig * 2;
        float v00 = acc[nt][0] * iv0, v01 = acc[nt][1] * iv0;
        float v10 = acc[nt][2] * iv1, v11 = acc[nt][3] * iv1;
        size_t o0 = (size_t)(i0 + r0) * (H * F) + col;
        size_t o1 = (size_t)(i0 + r1) * (H * F) + col;
        if (SPLIT) {
            __nv_bfloat162 h0 = __floats2bfloat162_rn(v00, v01);
            __nv_bfloat162 h1 = __floats2bfloat162_rn(v10, v11);
            __nv_bfloat162 l0 = __floats2bfloat162_rn(v00 - __bfloat162float(h0.x),
                                                      v01 - __bfloat162float(h0.y));
            __nv_bfloat162 l1 = __floats2bfloat162_rn(v10 - __bfloat162float(h1.x),
                                                      v11 - __bfloat162float(h1.y));
            *(__nv_bfloat162*)&ohi[o0] = h0;
            *(__nv_bfloat162*)&ohi[o1] = h1;
            *(__nv_bfloat162*)&olo[o0] = l0;
            *(__nv_bfloat162*)&olo[o1] = l1;
        } else {
            *(float2*)&out[o0] = make_float2(v00, v01);
            *(float2*)&out[o1] = make_float2(v10, v11);
        }
    }
}

// ---------------- batchnorm: per-block partials + fused fin/apply ----------------
template <int C>
__global__ void k_bn_part(const float* __restrict__ z, float* __restrict__ part) {
    constexpr int RL = 256 / C;
    int blk = blockIdx.x;
    int t = threadIdx.x;
    int col = t % C, rl = t / C;
    float s = 0.f, s2 = 0.f;
    for (int r = rl; r < 128; r += RL) {
        float v = z[(size_t)(blk * 128 + r) * C + col];
        s += v; s2 += v * v;
    }
    __shared__ float sh[256], sh2[256];
    sh[t] = s; sh2[t] = s2;
    __syncthreads();
    if (rl == 0) {
#pragma unroll
        for (int q = 1; q < RL; q++) { s += sh[q * C + col]; s2 += sh2[q * C + col]; }
        part[blk * 2 * C + col] = s;
        part[blk * 2 * C + C + col] = s2;
    }
}

// fused: recompute mean/rstd from partials in-block, then BN+ELU (+ optional split)
template <int C, bool SPLIT>
__global__ __launch_bounds__(256) void k_bn_elu_fused(
    const float* __restrict__ z, const float* __restrict__ part,
    const float* __restrict__ gamma, const float* __restrict__ beta,
    float* __restrict__ out, __nv_bfloat16* __restrict__ oh, __nv_bfloat16* __restrict__ ol) {
    __shared__ float smean[C], srstd[C];
    int t = threadIdx.x;
    if (t < C) {
        double s = 0.0, s2 = 0.0;
        for (int b = 0; b < 32; b++) {
            s += part[b * 2 * C + t];
            s2 += part[b * 2 * C + C + t];
        }
        double mu = s / NN;
        double var = s2 / NN - mu * mu;
        smean[t] = (float)mu;
        srstd[t] = rsqrtf((float)var + BN_EPS);
    }
    __syncthreads();
    int per = (NN * C) / gridDim.x;
    int base = blockIdx.x * per;
    for (int i = t; i < per; i += 256) {
        int idx = base + i;
        int c = idx % C;
        float v = (z[idx] - smean[c]) * srstd[c] * gamma[c] + beta[c];
        v = v > 0.f ? v : (expf(v) - 1.f);
        if (SPLIT) {
            __nv_bfloat16 hi = __float2bfloat16(v);
            oh[idx] = hi;
            ol[idx] = __float2bfloat16(v - __bfloat162float(hi));
        } else {
            out[idx] = v;
        }
    }
}

// ---------------- launch ----------------
extern "C" void kernel_launch(void* const* d_in, const int* in_sizes, int n_in,
                              void* d_out, int out_size) {
    const float* x   = (const float*)d_in[0];
    const int*   adj = (const int*)d_in[1];
    const float* W1  = (const float*)d_in[2];
    const float* a1s = (const float*)d_in[3];
    const float* a1d = (const float*)d_in[4];
    const float* lw1 = (const float*)d_in[5];
    const float* lb1 = (const float*)d_in[6];
    const float* g1  = (const float*)d_in[7];
    const float* be1 = (const float*)d_in[8];
    const float* W2  = (const float*)d_in[9];
    const float* a2s = (const float*)d_in[10];
    const float* a2d = (const float*)d_in[11];
    const float* lw2 = (const float*)d_in[12];
    const float* lb2 = (const float*)d_in[13];
    const float* g2  = (const float*)d_in[14];
    const float* be2 = (const float*)d_in[15];
    float* out = (float*)d_out;

    float *h1, *x2, *h2, *x3, *z4, *sc1, *sc2, *bnp;
    __half *sch1, *sch2, *h1th, *h2th;
    __nv_bfloat16 *ah, *al, *wth, *wtl, *lw1th, *lw1tl, *w2th, *w2tl;
    cudaGetSymbolAddress((void**)&h1, g_h1);
    cudaGetSymbolAddress((void**)&x2, g_x2);
    cudaGetSymbolAddress((void**)&h2, g_h2);
    cudaGetSymbolAddress((void**)&x3, g_x3);
    cudaGetSymbolAddress((void**)&z4, g_z4);
    cudaGetSymbolAddress((void**)&sc1, g_sc1);
    cudaGetSymbolAddress((void**)&sc2, g_sc2);
    cudaGetSymbolAddress((void**)&sch1, g_sch1);
    cudaGetSymbolAddress((void**)&sch2, g_sch2);
    cudaGetSymbolAddress((void**)&bnp, g_bnpart);
    cudaGetSymbolAddress((void**)&h1th, g_h1th);
    cudaGetSymbolAddress((void**)&h2th, g_h2th);
    cudaGetSymbolAddress((void**)&ah, g_ah);
    cudaGetSymbolAddress((void**)&al, g_al);
    cudaGetSymbolAddress((void**)&wth, g_wth);
    cudaGetSymbolAddress((void**)&wtl, g_wtl);
    cudaGetSymbolAddress((void**)&lw1th, g_lw1th);
    cudaGetSymbolAddress((void**)&lw1tl, g_lw1tl);
    cudaGetSymbolAddress((void**)&w2th, g_w2th);
    cudaGetSymbolAddress((void**)&w2tl, g_w2tl);

    const int SMEM1 = 3 * F1 * 128 + 3072 + 768;
    const int SMEM2 = 3 * F2 * 128 + 3072 + 768;
    const int SMEMG128 = 3 * (2 * 16384 + 2 * 128 * 128);
    const int SMEMG64  = 3 * (2 * 16384 + 2 * 64 * 128);
    cudaFuncSetAttribute((const void*)k_gat_hmma<F1, true>,
                         cudaFuncAttributeMaxDynamicSharedMemorySize, SMEM1);
    cudaFuncSetAttribute((const void*)k_gat_hmma<F2, false>,
                         cudaFuncAttributeMaxDynamicSharedMemorySize, SMEM2);
    cudaFuncSetAttribute((const void*)k_gemm_hmma<128, 16>,
                         cudaFuncAttributeMaxDynamicSharedMemorySize, SMEMG128);
    cudaFuncSetAttribute((const void*)k_gemm_hmma<64, 8>,
                         cudaFuncAttributeMaxDynamicSharedMemorySize, SMEMG64);

    static cudaStream_t s2 = nullptr;
    static cudaEvent_t e0 = nullptr, eW = nullptr, e2 = nullptr, e3 = nullptr,
                       e4 = nullptr, e5 = nullptr;
    if (!s2) {
        cudaStreamCreateWithFlags(&s2, cudaStreamNonBlocking);
        cudaEventCreateWithFlags(&e0, cudaEventDisableTiming);
        cudaEventCreateWithFlags(&eW, cudaEventDisableTiming);
        cudaEventCreateWithFlags(&e2, cudaEventDisableTiming);
        cudaEventCreateWithFlags(&e3, cudaEventDisableTiming);
        cudaEventCreateWithFlags(&e4, cudaEventDisableTiming);
        cudaEventCreateWithFlags(&e5, cudaEventDisableTiming);
    }

    // side stream: W1 transpose first (gemm1 needs it), then mask + other weights
    cudaEventRecord(e0, 0);
    cudaStreamWaitEvent(s2, e0, 0);
    k_transpose_split<<<dim3(IN_F / 32, 512 / 32), dim3(32, 8), 0, s2>>>(W1, wth, wtl, IN_F, 512);
    cudaEventRecord(eW, s2);
    k_pack_mask<<<(NN * NN) / 256, 256, 0, s2>>>(adj);
    k_transpose_split<<<dim3(512 / 32, HID1 / 32), dim3(32, 8), 0, s2>>>(lw1, lw1th, lw1tl, 512, HID1);
    k_transpose_split<<<dim3(HID1 / 32, 128 / 32), dim3(32, 8), 0, s2>>>(W2, w2th, w2tl, HID1, 128);

    // main: split x, join W1 transpose, gemm1
    k_split_bf16<<<(NN * IN_F / 4) / 256, 256>>>(x, ah, al);
    cudaStreamWaitEvent(0, eW, 0);
    k_gemm_hmma<128, 16><<<dim3(NN / 128, 512 / 128), 512, SMEMG128>>>(
        ah, al, wth, wtl, nullptr, h1, IN_F, 512);

    cudaEventRecord(e2, 0);
    cudaStreamWaitEvent(s2, e2, 0);
    k_transpose_f16<<<dim3(NN / 32, 512 / 32), dim3(32, 8), 0, s2>>>(h1, h1th, NN, 512);
    k_attn_scores<F1><<<NN / 8, 256>>>(h1, a1s, a1d, sc1, sch1);
    cudaEventRecord(e3, s2);
    cudaStreamWaitEvent(0, e3, 0);

    // gat1: full-K, writes normalized bf16 hi/lo directly into ah/al
    k_gat_hmma<F1, true><<<dim3(NN / 128, H), 256, SMEM1>>>(h1th, sc1, sch1, nullptr, ah, al);

    k_gemm_hmma<64, 8><<<dim3(NN / 128, HID1 / 64), 256, SMEMG64>>>(
        ah, al, lw1th, lw1tl, lb1, x2, 512, HID1);

    k_bn_part<HID1><<<32, 256>>>(x2, bnp);
    k_bn_elu_fused<HID1, true><<<64, 256>>>(x2, bnp, g1, be1, nullptr, ah, al);

    k_gemm_hmma<128, 16><<<dim3(NN / 128, 1), 512, SMEMG128>>>(
        ah, al, w2th, w2tl, nullptr, h2, HID1, 128);

    cudaEventRecord(e4, 0);
    cudaStreamWaitEvent(s2, e4, 0);
    k_transpose_f16<<<dim3(NN / 32, 128 / 32), dim3(32, 8), 0, s2>>>(h2, h2th, NN, 128);
    k_attn_scores<F2><<<NN / 8, 256>>>(h2, a2s, a2d, sc2, sch2);
    cudaEventRecord(e5, s2);
    cudaStreamWaitEvent(0, e5, 0);

    // gat2: full-K, writes normalized fp32 x3 directly
    k_gat_hmma<F2, false><<<dim3(NN / 128, H), 256, SMEM2>>>(h2th, sc2, sch2, x3, nullptr, nullptr);

    k_gemm_bias<128, 16, 32, 4, 2><<<dim3(1, NN / 128), 256>>>(x3, lw2, lb2, z4, NN, OUT_F, 128);

    k_bn_part<OUT_F><<<32, 256>>>(z4, bnp);
    k_bn_elu_fused<OUT_F, false><<<64, 256>>>(z4, bnp, g2, be2, out, nullptr, nullptr);
}